// round 10
// baseline (speedup 1.0000x reference)
#include <cuda_runtime.h>
#include <cuda_fp16.h>
#include <stdint.h>

#define NTOK  16384
#define DPROJ 1024
#define BM 128
#define BN 128
#define BK 32            // k halves per stage
#define HSTRIDE 40       // half row stride (20 words; conflict-free ldmatrix)
#define STAGES 4
#define MAX_MTILES 132

// A fp16 regions, indexed by flat token position t
#define A0 0UL
#define A1 (A0 + 16384UL * 1024)
#define A2 (A1 + 16384UL * 256)
#define A3 (A2 + 16384UL * 64)
#define ATOT (A3 + 16384UL * 16)
// B fp16 regions
#define B0 0UL
#define B1 (B0 + 1024UL * 1024)
#define B2 (B1 + 1024UL * 256)
#define B3 (B2 + 1024UL * 64)
#define BTOT (B3 + 1024UL * 16)

#define NB16 (BTOT / 16)
#define NA16 (NTOK * 64UL)

__device__ int g_count[4];
__device__ int g_perm[4 * NTOK];
__device__ __half g_ah[ATOT];
__device__ __half g_bh[BTOT];

__device__ __forceinline__ uint4 pack8(float4 v0, float4 v1) {
    __half2 h0 = __float22half2_rn(make_float2(v0.x, v0.y));
    __half2 h1 = __float22half2_rn(make_float2(v0.z, v0.w));
    __half2 h2 = __float22half2_rn(make_float2(v1.x, v1.y));
    __half2 h3 = __float22half2_rn(make_float2(v1.z, v1.w));
    uint4 r;
    r.x = *(uint32_t*)&h0; r.y = *(uint32_t*)&h1;
    r.z = *(uint32_t*)&h2; r.w = *(uint32_t*)&h3;
    return r;
}

__device__ __forceinline__ void conv16(const float* s, __half* d) {
    float4 v0 = *(const float4*)(s);
    float4 v1 = *(const float4*)(s + 4);
    float4 v2 = *(const float4*)(s + 8);
    float4 v3 = *(const float4*)(s + 12);
    *(uint4*)d       = pack8(v0, v1);
    *(uint4*)(d + 8) = pack8(v2, v3);
}

__global__ void k_prep(const int* __restrict__ inp,
                       const float* __restrict__ e0, const float* __restrict__ e1,
                       const float* __restrict__ e2, const float* __restrict__ e3,
                       const float* __restrict__ p0, const float* __restrict__ p1,
                       const float* __restrict__ p2, const float* __restrict__ p3)
{
    const int tid = threadIdx.x;
    const int b   = blockIdx.x;

    if (b < NTOK / 256) {
        int t = b * 256 + tid;
        int tok = inp[t];
        int c = (tok >= 200000) ? 3 : (tok >= 40000) ? 2 : (tok >= 20000) ? 1 : 0;
        unsigned m = __match_any_sync(0xffffffffu, c);
        int lane = tid & 31;
        int leader = __ffs(m) - 1;
        int base = 0;
        if (lane == leader) base = atomicAdd(&g_count[c], __popc(m));
        base = __shfl_sync(0xffffffffu, base, leader);
        int rank = __popc(m & ((1u << lane) - 1));
        g_perm[c * NTOK + base + rank] = t;
    }

    const size_t stride = (size_t)gridDim.x * blockDim.x;
    for (size_t u = (size_t)b * blockDim.x + tid; u < NB16 + NA16; u += stride) {
        if (u < NB16) {
            size_t e = u * 16;
            const float* p; size_t off;
            if (e < B1)      { p = p0; off = e - B0; }
            else if (e < B2) { p = p1; off = e - B1; }
            else if (e < B3) { p = p2; off = e - B2; }
            else             { p = p3; off = e - B3; }
            conv16(p + off, g_bh + e);
        } else {
            size_t w = u - NB16;
            int t    = (int)(w >> 6);
            int koff = (int)(w & 63) << 4;
            int tok  = inp[t];
            const float* src; int D, lo; size_t baseA;
            if      (tok < 20000)  { src = e0; D = 1024; lo = 0;      baseA = A0; }
            else if (tok < 40000)  { src = e1; D = 256;  lo = 20000;  baseA = A1; }
            else if (tok < 200000) { src = e2; D = 64;   lo = 40000;  baseA = A2; }
            else                   { src = e3; D = 16;   lo = 200000; baseA = A3; }
            if (koff < D)
                conv16(src + (size_t)(tok - lo) * D + koff,
                       g_ah + baseA + (size_t)t * D + koff);
        }
    }
}

__device__ __forceinline__ void cp16(uint32_t dst, const void* src, int valid) {
    asm volatile("cp.async.cg.shared.global [%0], [%1], 16, %2;"
                 :: "r"(dst), "l"(src), "r"(valid));
}
__device__ __forceinline__ void ldm4(uint32_t& r0, uint32_t& r1,
                                     uint32_t& r2, uint32_t& r3, uint32_t addr) {
    asm volatile("ldmatrix.sync.aligned.m8n8.x4.shared.b16 {%0,%1,%2,%3}, [%4];"
                 : "=r"(r0), "=r"(r1), "=r"(r2), "=r"(r3) : "r"(addr));
}

// Fused GEMM: 128 threads, 4 warps, warp tile 64x64 (2x2 grid), block 128x128.
__global__ void __launch_bounds__(128, 2)
k_fused(float* __restrict__ out)
{
    extern __shared__ __half smh[];
    __half* As = smh;                                   // [STAGES][BM][HSTRIDE]
    __half* Bs = smh + STAGES * BM * HSTRIDE;           // [STAGES][BN][HSTRIDE]
    int* s_tok = (int*)(Bs + STAGES * BN * HSTRIDE);    // [BM]

    int y = blockIdx.y;
    int cluster = -1, mtile = 0, acc = 0;
#pragma unroll
    for (int c = 0; c < 4; c++) {
        int tiles = (g_count[c] + BM - 1) >> 7;
        if (cluster < 0 && y < acc + tiles) { cluster = c; mtile = y - acc; }
        acc += tiles;
    }
    if (cluster < 0) return;

    int D; size_t baseA, baseB;
    switch (cluster) {
        case 0:  D = 1024; baseA = A0; baseB = B0; break;
        case 1:  D = 256;  baseA = A1; baseB = B1; break;
        case 2:  D = 64;   baseA = A2; baseB = B2; break;
        default: D = 16;   baseA = A3; baseB = B3; break;
    }

    const int tid = threadIdx.x;
    const int cnt = g_count[cluster];

    {
        int m = mtile * BM + tid;
        s_tok[tid] = (m < cnt) ? g_perm[cluster * NTOK + m] : -1;
    }
    __syncthreads();

    // ---- loader: each thread owns one A row and one B row (32 halves/stage) ----
    const int nb = blockIdx.x * BN;
    const int atok = s_tok[tid];
    const int arow_ok = (atok >= 0);
    const __half* asrc = g_ah + baseA + (size_t)(arow_ok ? atok : 0) * D;
    const __half* bsrc = g_bh + baseB + (size_t)(nb + tid) * D;

    const uint32_t a_smem = (uint32_t)__cvta_generic_to_shared(As) + tid * (HSTRIDE * 2);
    const uint32_t b_smem = (uint32_t)__cvta_generic_to_shared(Bs) + tid * (HSTRIDE * 2);

    const int nk = (D + BK - 1) / BK;

// 32 halves/row/stage = 4x 16B cp.async per operand (8-half chunks at 0,8,16,24)
#define ISSUE(kbi)                                                            \
    do {                                                                      \
        int _buf = (kbi) % STAGES;                                            \
        int _kb  = (kbi) * BK;                                                \
        int _v1  = (_kb      < D) ? 16 : 0;   /* halves [0,16)  */            \
        int _v2  = (_kb + 16 < D) ? 16 : 0;   /* halves [16,32) */            \
        int _va1 = arow_ok ? _v1 : 0;                                         \
        int _va2 = arow_ok ? _v2 : 0;                                         \
        uint32_t _ad = a_smem + _buf * (BM * HSTRIDE * 2);                    \
        uint32_t _bd = b_smem + _buf * (BN * HSTRIDE * 2);                    \
        cp16(_ad,      asrc + _kb,      _va1);                                \
        cp16(_ad + 16, asrc + _kb + 8,  _va1);                                \
        cp16(_ad + 32, asrc + _kb + 16, _va2);                                \
        cp16(_ad + 48, asrc + _kb + 24, _va2);                                \
        cp16(_bd,      bsrc + _kb,      _v1);                                 \
        cp16(_bd + 16, bsrc + _kb + 8,  _v1);                                 \
        cp16(_bd + 32, bsrc + _kb + 16, _v2);                                 \
        cp16(_bd + 48, bsrc + _kb + 24, _v2);                                 \
    } while (0)

#pragma unroll
    for (int s = 0; s < STAGES - 1; s++) {
        if (s < nk) ISSUE(s);
        asm volatile("cp.async.commit_group;");
    }

    // ---- warp / fragment mapping: 4 warps = 2m x 2n, warp tile 64x64 ----
    const int wid  = tid >> 5, lane = tid & 31;
    const int gid  = lane >> 2, tg = lane & 3;
    const int wm   = (wid >> 1) * 64;
    const int wn   = (wid & 1) * 64;

    const int l8   = lane & 7;
    const int lb8  = (lane >> 3) & 1;
    const int lb16 = (lane >> 4) & 1;
    uint32_t a_off[4], b_off[4];
#pragma unroll
    for (int mi = 0; mi < 4; mi++)
        a_off[mi] = ((wm + mi * 16 + lb8 * 8 + l8) * HSTRIDE + lb16 * 8) * 2;
#pragma unroll
    for (int j = 0; j < 4; j++)
        b_off[j] = ((wn + j * 16 + lb16 * 8 + l8) * HSTRIDE + lb8 * 8) * 2;

    const uint32_t As_u = (uint32_t)__cvta_generic_to_shared(As);
    const uint32_t Bs_u = (uint32_t)__cvta_generic_to_shared(Bs);

    float accum[4][8][4];
#pragma unroll
    for (int i = 0; i < 4; i++)
#pragma unroll
        for (int j = 0; j < 8; j++)
#pragma unroll
            for (int k = 0; k < 4; k++) accum[i][j][k] = 0.f;

    for (int kbi = 0; kbi < nk; kbi++) {
        asm volatile("cp.async.wait_group 2;");
        __syncthreads();

        const uint32_t Abu = As_u + (kbi % STAGES) * (BM * HSTRIDE * 2);
        const uint32_t Bbu = Bs_u + (kbi % STAGES) * (BN * HSTRIDE * 2);

#pragma unroll
        for (int ks = 0; ks < 2; ks++) {
            const int kkb = ks * 32;   // byte offset of 16-half sub-block
            uint32_t a[4][4], b[8][2];
#pragma unroll
            for (int mi = 0; mi < 4; mi++)
                ldm4(a[mi][0], a[mi][1], a[mi][2], a[mi][3], Abu + a_off[mi] + kkb);
#pragma unroll
            for (int j = 0; j < 4; j++)
                ldm4(b[2*j][0], b[2*j][1], b[2*j+1][0], b[2*j+1][1],
                     Bbu + b_off[j] + kkb);
#pragma unroll
            for (int mi = 0; mi < 4; mi++)
#pragma unroll
                for (int ni = 0; ni < 8; ni++) {
                    asm volatile(
                        "mma.sync.aligned.m16n8k16.row.col.f32.f16.f16.f32 "
                        "{%0,%1,%2,%3}, {%4,%5,%6,%7}, {%8,%9}, {%0,%1,%2,%3};"
                        : "+f"(accum[mi][ni][0]), "+f"(accum[mi][ni][1]),
                          "+f"(accum[mi][ni][2]), "+f"(accum[mi][ni][3])
                        : "r"(a[mi][0]), "r"(a[mi][1]), "r"(a[mi][2]), "r"(a[mi][3]),
                          "r"(b[ni][0]), "r"(b[ni][1]));
                }
        }

        int pf = kbi + STAGES - 1;
        if (pf < nk) ISSUE(pf);
        asm volatile("cp.async.commit_group;");
    }
#undef ISSUE

    // ---- epilogue: scale by 32, scatter to out[token, :] ----
#pragma unroll
    for (int mi = 0; mi < 4; mi++) {
#pragma unroll
        for (int half = 0; half < 2; half++) {
            int rl = wm + mi * 16 + gid + half * 8;
            int t  = s_tok[rl];
            if (t >= 0) {
                float* op = out + (size_t)t * DPROJ + nb + wn;
#pragma unroll
                for (int ni = 0; ni < 8; ni++) {
                    float2 v;
                    v.x = accum[mi][ni][half * 2 + 0] * 32.f;
                    v.y = accum[mi][ni][half * 2 + 1] * 32.f;
                    *(float2*)(op + ni * 8 + tg * 2) = v;
                }
            }
        }
    }
}

extern "C" void kernel_launch(void* const* d_in, const int* in_sizes, int n_in,
                              void* d_out, int out_size) {
    const int*   inp   = (const int*)d_in[0];
    const float* emb0  = (const float*)d_in[1];
    const float* proj0 = (const float*)d_in[2];
    const float* emb1  = (const float*)d_in[3];
    const float* proj1 = (const float*)d_in[4];
    const float* emb2  = (const float*)d_in[5];
    const float* proj2 = (const float*)d_in[6];
    const float* emb3  = (const float*)d_in[7];
    const float* proj3 = (const float*)d_in[8];
    float* out = (float*)d_out;

    const int smem_bytes = STAGES * (BM + BN) * HSTRIDE * 2 + BM * 4;
    cudaFuncSetAttribute(k_fused, cudaFuncAttributeMaxDynamicSharedMemorySize,
                         smem_bytes);

    void* gcnt = nullptr;
    cudaGetSymbolAddress(&gcnt, g_count);
    cudaMemsetAsync(gcnt, 0, 4 * sizeof(int));

    k_prep<<<1024, 256>>>(inp, emb0, emb1, emb2, emb3,
                          proj0, proj1, proj2, proj3);

    dim3 grid(DPROJ / BN, MAX_MTILES);   // (8, 132)
    k_fused<<<grid, 128, smem_bytes>>>(out);
}